// round 2
// baseline (speedup 1.0000x reference)
#include <cuda_runtime.h>

// Problem constants (fixed by reference setup_inputs)
#define NB    64
#define NA    5
#define NC    80
#define NH    38
#define NW    38
#define CELLS (NH*NW)          // 1444
#define NBOX  50
#define CH    (5+NC)           // 85
#define BLK   256
#define CPT   2                           // cells per thread
#define GX    ((CELLS + BLK*CPT - 1)/(BLK*CPT))   // 3
#define NBLOCKS (GX*NB*NA)                // 960

__constant__ float c_aw[5] = {1.3221f, 3.19275f, 5.05587f, 9.47112f, 11.2364f};
__constant__ float c_ah[5] = {1.73145f, 4.00944f, 8.09892f, 4.84053f, 10.0071f};

__device__ float g_partial[NBLOCKS];
__device__ int   g_count = 0;

__device__ __forceinline__ float fsigmoid(float x) {
    return 1.0f / (1.0f + __expf(-x));
}

__global__ void __launch_bounds__(BLK) region_fused(const float* __restrict__ out,
                                                    const float* __restrict__ target,
                                                    float* __restrict__ result) {
    // Per-GT-box data shared across the block (one (b, a) slice per blockIdx.y)
    __shared__ float sx1[NBOX], sx2[NBOX], sy1[NBOX], sy2[NBOX];
    __shared__ float sthr[NBOX], sarea[NBOX];
    __shared__ float stcx[NBOX], stcy[NBOX], stcw[NBOX], stch[NBOX], scm[NBOX];
    __shared__ int   sfidx[NBOX], scls[NBOX], svalid[NBOX];
    __shared__ int   snv;

    const int ba  = blockIdx.y;       // b*NA + a
    const int b   = ba / NA;
    const int a   = ba - b * NA;
    const int tid = threadIdx.x;

    if (tid < NBOX) {
        const float* tb = target + b * (NBOX * 5) + tid * 5;
        float cls = tb[0], x = tb[1], y = tb[2], w = tb[3], h = tb[4];
        svalid[tid] = (x > 0.0f) ? 1 : 0;
        float gx = x * NW, gy = y * NH, gw = w * NW, gh = h * NH;
        // best anchor by shape IoU (first max wins, matching jnp.argmax)
        int best = 0; float bestv = -1.0f;
        #pragma unroll
        for (int k = 0; k < 5; k++) {
            float aw = c_aw[k], ah = c_ah[k];
            float inter = fminf(aw, gw) * fminf(ah, gh);
            float uni   = aw * ah + gw * gh - inter;
            float v     = inter / fmaxf(uni, 1e-10f);
            if (v > bestv) { bestv = v; best = k; }
        }
        int gi = min(max((int)gx, 0), NW - 1);
        int gj = min(max((int)gy, 0), NH - 1);
        sfidx[tid] = ((b * NA + best) * NH + gj) * NW + gi;
        float ga = gw * gh;
        sx1[tid] = gx - 0.5f * gw;  sx2[tid] = gx + 0.5f * gw;
        sy1[tid] = gy - 0.5f * gh;  sy2[tid] = gy + 0.5f * gh;
        sarea[tid] = ga;
        sthr[tid]  = 0.375f * ga;          // iou>0.6  <=>  inter - 0.375*parea > 0.375*garea
        stcx[tid] = gx - (float)gi;
        stcy[tid] = gy - (float)gj;
        stcw[tid] = __logf(gw / c_aw[best]);
        stch[tid] = __logf(gh / c_ah[best]);
        scm[tid]  = 2.0f - w * h;
        scls[tid] = (int)cls;
    }
    __syncthreads();
    if (tid == 0) {
        int nv = 0;
        while (nv < NBOX && svalid[nv]) nv++;   // cumprod validity prefix
        snv = nv;
    }
    __syncthreads();
    const int nv = snv;

    // ---- per-thread: CPT cells ----
    float ax1[CPT], ax2[CPT], ay1[CPT], ay2[CPT], c375[CPT], parea[CPT];
    float vsx[CPT], vsy[CPT], vtw[CPT], vth[CPT], vconf[CPT];
    int   nn[CPT], win[CPT];
    bool  over[CPT], act[CPT];

    #pragma unroll
    for (int u = 0; u < CPT; u++) {
        const int cell = blockIdx.x * (BLK * CPT) + u * BLK + tid;
        act[u] = (cell < CELLS);
        win[u] = -1;
        over[u] = false;
        if (act[u]) {
            const int base = (ba * CH) * CELLS + cell;
            float tx = out[base];
            float ty = out[base + CELLS];
            float tw = out[base + 2 * CELLS];
            float th = out[base + 3 * CELLS];
            float to = out[base + 4 * CELLS];
            float sx = fsigmoid(tx), sy = fsigmoid(ty);
            vsx[u] = sx; vsy[u] = sy; vtw[u] = tw; vth[u] = th;
            vconf[u] = fsigmoid(to);
            const int i = cell % NW, j = cell / NW;
            float px = sx + (float)i, py = sy + (float)j;
            float pw = __expf(tw) * c_aw[a], ph = __expf(th) * c_ah[a];
            ax1[u] = px - 0.5f * pw;  ax2[u] = px + 0.5f * pw;
            ay1[u] = py - 0.5f * ph;  ay2[u] = py + 0.5f * ph;
            parea[u] = pw * ph;
            c375[u]  = 0.375f * pw * ph;
            nn[u] = ba * CELLS + cell;
        } else {
            ax1[u] = ax2[u] = ay1[u] = ay2[u] = 0.0f;
            c375[u] = 1e30f; parea[u] = 0.0f;
            vsx[u] = vsy[u] = vtw[u] = vth[u] = vconf[u] = 0.0f;
            nn[u] = -1;
        }
    }

    for (int t = 0; t < nv; t++) {
        const float bx1 = sx1[t], bx2 = sx2[t];
        const float by1 = sy1[t], by2 = sy2[t];
        const float bthr = sthr[t];
        const int   bf   = sfidx[t];
        #pragma unroll
        for (int u = 0; u < CPT; u++) {
            float iw = fminf(ax2[u], bx2) - fmaxf(ax1[u], bx1);
            float ih = fminf(ay2[u], by2) - fmaxf(ay1[u], by1);
            float inter = fmaxf(iw, 0.0f) * fmaxf(ih, 0.0f);
            over[u] = over[u] | ((inter - c375[u]) > bthr);
            if (bf == nn[u]) win[u] = t;      // last-write-wins scatter
        }
    }

    float acc = 0.0f;
    #pragma unroll
    for (int u = 0; u < CPT; u++) {
        if (!act[u]) continue;
        float lcoord, lconf, lcls = 0.0f;
        const int w = win[u];
        if (w >= 0) {
            float cm = scm[w];
            float d0 = (vsx[u] - stcx[w]) * cm;
            float d1 = (vsy[u] - stcy[w]) * cm;
            float d2 = (vtw[u] - stcw[w]) * cm;
            float d3 = (vth[u] - stch[w]) * cm;
            lcoord = d0 * d0 + d1 * d1 + d2 * d2 + d3 * d3;

            float iw = fminf(ax2[u], sx2[w]) - fmaxf(ax1[u], sx1[w]);
            float ih = fminf(ay2[u], sy2[w]) - fmaxf(ay1[u], sy1[w]);
            float inter = fmaxf(iw, 0.0f) * fmaxf(ih, 0.0f);
            float uni   = parea[u] + sarea[w] - inter;
            float iou   = inter / fmaxf(uni, 1e-10f);
            float dc = (vconf[u] - iou) * 5.0f;
            lconf = dc * dc;

            // class CE: single-pass log-sum-exp (|logits|<~6, no overflow risk)
            const int cell = blockIdx.x * (BLK * CPT) + u * BLK + tid;
            const int cb = (ba * CH + 5) * CELLS + cell;
            const int kc = scls[w];
            float s = 0.0f, lc = 0.0f;
            #pragma unroll 4
            for (int k = 0; k < NC; k++) {
                float v = out[cb + k * CELLS];
                s += __expf(v);
                if (k == kc) lc = v;
            }
            lcls = __logf(s) - lc;
        } else {
            float d0 = (vsx[u] - 0.5f) * 0.01f;
            float d1 = (vsy[u] - 0.5f) * 0.01f;
            float d2 = vtw[u] * 0.01f;
            float d3 = vth[u] * 0.01f;
            lcoord = d0 * d0 + d1 * d1 + d2 * d2 + d3 * d3;
            float dc = over[u] ? 0.0f : vconf[u];
            lconf = dc * dc;
        }
        acc += lcoord + lconf + lcls;
    }

    // deterministic block reduction -> per-block partial
    __shared__ float red[BLK];
    red[tid] = acc;
    __syncthreads();
    #pragma unroll
    for (int s = BLK / 2; s >= 32; s >>= 1) {
        if (tid < s) red[tid] += red[tid + s];
        __syncthreads();
    }
    if (tid < 32) {
        float v = red[tid];
        #pragma unroll
        for (int o = 16; o > 0; o >>= 1)
            v += __shfl_down_sync(0xffffffffu, v, o);
        if (tid == 0) g_partial[blockIdx.y * GX + blockIdx.x] = v;
    }

    // last-block-done final reduce (deterministic order)
    __shared__ int s_last;
    if (tid == 0) {
        __threadfence();
        int prev = atomicAdd(&g_count, 1);
        s_last = (prev == NBLOCKS - 1) ? 1 : 0;
    }
    __syncthreads();
    if (s_last) {
        __threadfence();
        float s = 0.0f;
        for (int i = tid; i < NBLOCKS; i += BLK)
            s += ((volatile float*)g_partial)[i];
        red[tid] = s;
        __syncthreads();
        #pragma unroll
        for (int k = BLK / 2; k >= 32; k >>= 1) {
            if (tid < k) red[tid] += red[tid + k];
            __syncthreads();
        }
        if (tid < 32) {
            float v = red[tid];
            #pragma unroll
            for (int o = 16; o > 0; o >>= 1)
                v += __shfl_down_sync(0xffffffffu, v, o);
            if (tid == 0) {
                result[0] = v * (1.0f / (float)NB);
                g_count = 0;   // reset for next graph replay
            }
        }
    }
}

extern "C" void kernel_launch(void* const* d_in, const int* in_sizes, int n_in,
                              void* d_out, int out_size) {
    const float* output = (const float*)d_in[0];
    const float* target = (const float*)d_in[1];
    float* outp = (float*)d_out;

    dim3 grid(GX, NB * NA);
    region_fused<<<grid, BLK>>>(output, target, outp);
}

// round 3
// speedup vs baseline: 1.0529x; 1.0529x over previous
#include <cuda_runtime.h>

// Problem constants (fixed by reference setup_inputs)
#define NB    64
#define NA    5
#define NC    80
#define NH    38
#define NW    38
#define CELLS (NH*NW)          // 1444
#define NBOX  50
#define CH    (5+NC)           // 85
#define BLK   256
#define CPT   2                           // cells per thread
#define CPB   (BLK*CPT)                   // 512 cells per block
#define GX    ((CELLS + CPB - 1)/CPB)     // 3
#define NBLOCKS (GX*NB*NA)                // 960

__constant__ float c_aw[5] = {1.3221f, 3.19275f, 5.05587f, 9.47112f, 11.2364f};
__constant__ float c_ah[5] = {1.73145f, 4.00944f, 8.09892f, 4.84053f, 10.0071f};

__device__ float g_partial[NBLOCKS];
__device__ int   g_count = 0;

__device__ __forceinline__ float fsigmoid(float x) {
    return 1.0f / (1.0f + __expf(-x));
}

__global__ void __launch_bounds__(BLK, 6)
region_fused(const float* __restrict__ out,
             const float* __restrict__ target,
             float* __restrict__ result) {
    // Per-GT-box data (padded +1 so the t+1 prefetch never reads OOB)
    __shared__ float sx1[NBOX+1], sx2[NBOX+1], sy1[NBOX+1], sy2[NBOX+1], sthr[NBOX+1];
    __shared__ float sarea[NBOX], stcx[NBOX], stcy[NBOX], stcw[NBOX], stch[NBOX], scm[NBOX];
    __shared__ int   sfidx[NBOX], scls[NBOX], svalid[NBOX];
    __shared__ short swin[CPB];          // per-local-cell winner box (last-write-wins)
    __shared__ int   snv;

    const int ba  = blockIdx.y;       // b*NA + a
    const int b   = ba / NA;
    const int a   = ba - b * NA;
    const int tid = threadIdx.x;

    // init winner map
    swin[tid] = -1;
    swin[tid + BLK] = -1;

    if (tid < NBOX) {
        const float* tb = target + b * (NBOX * 5) + tid * 5;
        float cls = tb[0], x = tb[1], y = tb[2], w = tb[3], h = tb[4];
        svalid[tid] = (x > 0.0f) ? 1 : 0;
        float gx = x * NW, gy = y * NH, gw = w * NW, gh = h * NH;
        // best anchor by shape IoU (first max wins, matching jnp.argmax)
        int best = 0; float bestv = -1.0f;
        #pragma unroll
        for (int k = 0; k < 5; k++) {
            float aw = c_aw[k], ah = c_ah[k];
            float inter = fminf(aw, gw) * fminf(ah, gh);
            float uni   = aw * ah + gw * gh - inter;
            float v     = inter / fmaxf(uni, 1e-10f);
            if (v > bestv) { bestv = v; best = k; }
        }
        int gi = min(max((int)gx, 0), NW - 1);
        int gj = min(max((int)gy, 0), NH - 1);
        sfidx[tid] = ((b * NA + best) * NH + gj) * NW + gi;
        float ga = gw * gh;
        sx1[tid] = gx - 0.5f * gw;  sx2[tid] = gx + 0.5f * gw;
        sy1[tid] = gy - 0.5f * gh;  sy2[tid] = gy + 0.5f * gh;
        sarea[tid] = ga;
        sthr[tid]  = 0.375f * ga;      // iou>0.6  <=>  inter > 0.375*(parea+garea)
        stcx[tid] = gx - (float)gi;
        stcy[tid] = gy - (float)gj;
        stcw[tid] = __logf(gw / c_aw[best]);
        stch[tid] = __logf(gh / c_ah[best]);
        scm[tid]  = 2.0f - w * h;
        scls[tid] = (int)cls;
    }
    __syncthreads();
    if (tid == 0) {
        int nv = 0;
        while (nv < NBOX && svalid[nv]) nv++;   // cumprod validity prefix
        snv = nv;
        // pad prefetch slot
        sx1[nv] = 0.f; sx2[nv] = 0.f; sy1[nv] = 0.f; sy2[nv] = 0.f; sthr[nv] = 0.f;
        // scatter winners for this block's cell range (serial => last-write-wins)
        const int cell0 = blockIdx.x * CPB + ba * CELLS;   // global fidx base
        for (int t = 0; t < nv; t++) {
            int rel = sfidx[t] - cell0;
            if (rel >= 0 && rel < CPB) swin[rel] = (short)t;
        }
    }
    __syncthreads();
    const int nv = snv;

    // ---- per-thread: CPT cells ----
    float ax1[CPT], ax2[CPT], ay1[CPT], ay2[CPT], thrP[CPT];
    float vsx[CPT], vsy[CPT], vtw[CPT], vth[CPT], vconf[CPT];

    #pragma unroll
    for (int u = 0; u < CPT; u++) {
        const int cell = blockIdx.x * CPB + u * BLK + tid;
        if (cell < CELLS) {
            const int base = (ba * CH) * CELLS + cell;
            float tx = out[base];
            float ty = out[base + CELLS];
            float tw = out[base + 2 * CELLS];
            float th = out[base + 3 * CELLS];
            float to = out[base + 4 * CELLS];
            float sx = fsigmoid(tx), sy = fsigmoid(ty);
            vsx[u] = sx; vsy[u] = sy; vtw[u] = tw; vth[u] = th;
            vconf[u] = fsigmoid(to);
            const int i = cell % NW, j = cell / NW;
            float px = sx + (float)i, py = sy + (float)j;
            float pw = __expf(tw) * c_aw[a], ph = __expf(th) * c_ah[a];
            ax1[u] = px - 0.5f * pw;  ax2[u] = px + 0.5f * pw;
            ay1[u] = py - 0.5f * ph;  ay2[u] = py + 0.5f * ph;
            thrP[u] = 0.375f * (pw * ph);
        } else {
            ax1[u] = ax2[u] = ay1[u] = ay2[u] = 0.0f;
            thrP[u] = 1e30f;
            vsx[u] = vsy[u] = vtw[u] = vth[u] = vconf[u] = 0.0f;
        }
    }

    // hot loop: max-accumulate the over-threshold margin, software-pipelined
    float m0 = -1e30f, m1 = -1e30f;
    float nbx1 = sx1[0], nbx2 = sx2[0], nby1 = sy1[0], nby2 = sy2[0], nbt = sthr[0];
    #pragma unroll 2
    for (int t = 0; t < nv; t++) {
        const float bx1 = nbx1, bx2 = nbx2, by1 = nby1, by2 = nby2, bt = nbt;
        nbx1 = sx1[t+1]; nbx2 = sx2[t+1]; nby1 = sy1[t+1]; nby2 = sy2[t+1]; nbt = sthr[t+1];
        {
            float iw = fminf(ax2[0], bx2) - fmaxf(ax1[0], bx1);
            float ih = fminf(ay2[0], by2) - fmaxf(ay1[0], by1);
            float iwc = fmaxf(iw, 0.0f), ihc = fmaxf(ih, 0.0f);
            m0 = fmaxf(m0, fmaf(iwc, ihc, -(bt + thrP[0])));
        }
        {
            float iw = fminf(ax2[1], bx2) - fmaxf(ax1[1], bx1);
            float ih = fminf(ay2[1], by2) - fmaxf(ay1[1], by1);
            float iwc = fmaxf(iw, 0.0f), ihc = fmaxf(ih, 0.0f);
            m1 = fmaxf(m1, fmaf(iwc, ihc, -(bt + thrP[1])));
        }
    }

    float acc = 0.0f;
    #pragma unroll
    for (int u = 0; u < CPT; u++) {
        const int cell = blockIdx.x * CPB + u * BLK + tid;
        if (cell >= CELLS) continue;
        const float mu = (u == 0) ? m0 : m1;
        const int w = (int)swin[u * BLK + tid];
        float lcoord, lconf, lcls = 0.0f;
        if (w >= 0) {
            float cm = scm[w];
            float d0 = (vsx[u] - stcx[w]) * cm;
            float d1 = (vsy[u] - stcy[w]) * cm;
            float d2 = (vtw[u] - stcw[w]) * cm;
            float d3 = (vth[u] - stch[w]) * cm;
            lcoord = d0 * d0 + d1 * d1 + d2 * d2 + d3 * d3;

            float iw = fminf(ax2[u], sx2[w]) - fmaxf(ax1[u], sx1[w]);
            float ih = fminf(ay2[u], sy2[w]) - fmaxf(ay1[u], sy1[w]);
            float inter = fmaxf(iw, 0.0f) * fmaxf(ih, 0.0f);
            float parea = thrP[u] * (1.0f / 0.375f);
            float uni   = parea + sarea[w] - inter;
            float iou   = inter / fmaxf(uni, 1e-10f);
            float dc = (vconf[u] - iou) * 5.0f;
            lconf = dc * dc;

            // class CE: single-pass log-sum-exp (logits are ~N(0,1), no overflow)
            const int cb = (ba * CH + 5) * CELLS + cell;
            const int kc = scls[w];
            float s = 0.0f, lc = 0.0f;
            #pragma unroll 4
            for (int k = 0; k < NC; k++) {
                float v = out[cb + k * CELLS];
                s += __expf(v);
                lc = (k == kc) ? v : lc;
            }
            lcls = __logf(s) - lc;
        } else {
            float d0 = (vsx[u] - 0.5f) * 0.01f;
            float d1 = (vsy[u] - 0.5f) * 0.01f;
            float d2 = vtw[u] * 0.01f;
            float d3 = vth[u] * 0.01f;
            lcoord = d0 * d0 + d1 * d1 + d2 * d2 + d3 * d3;
            float dc = (mu > 0.0f) ? 0.0f : vconf[u];   // noobj iff max_iou <= 0.6
            lconf = dc * dc;
        }
        acc += lcoord + lconf + lcls;
    }

    // deterministic block reduction -> per-block partial
    __shared__ float red[BLK];
    red[tid] = acc;
    __syncthreads();
    #pragma unroll
    for (int s = BLK / 2; s >= 32; s >>= 1) {
        if (tid < s) red[tid] += red[tid + s];
        __syncthreads();
    }
    if (tid < 32) {
        float v = red[tid];
        #pragma unroll
        for (int o = 16; o > 0; o >>= 1)
            v += __shfl_down_sync(0xffffffffu, v, o);
        if (tid == 0) g_partial[blockIdx.y * GX + blockIdx.x] = v;
    }

    // last-block-done final reduce (deterministic order)
    __shared__ int s_last;
    if (tid == 0) {
        __threadfence();
        int prev = atomicAdd(&g_count, 1);
        s_last = (prev == NBLOCKS - 1) ? 1 : 0;
    }
    __syncthreads();
    if (s_last) {
        __threadfence();
        float s = 0.0f;
        for (int i = tid; i < NBLOCKS; i += BLK)
            s += ((volatile float*)g_partial)[i];
        red[tid] = s;
        __syncthreads();
        #pragma unroll
        for (int k = BLK / 2; k >= 32; k >>= 1) {
            if (tid < k) red[tid] += red[tid + k];
            __syncthreads();
        }
        if (tid < 32) {
            float v = red[tid];
            #pragma unroll
            for (int o = 16; o > 0; o >>= 1)
                v += __shfl_down_sync(0xffffffffu, v, o);
            if (tid == 0) {
                result[0] = v * (1.0f / (float)NB);
                g_count = 0;   // reset for next graph replay
            }
        }
    }
}

extern "C" void kernel_launch(void* const* d_in, const int* in_sizes, int n_in,
                              void* d_out, int out_size) {
    const float* output = (const float*)d_in[0];
    const float* target = (const float*)d_in[1];
    float* outp = (float*)d_out;

    dim3 grid(GX, NB * NA);
    region_fused<<<grid, BLK>>>(output, target, outp);
}